// round 13
// baseline (speedup 1.0000x reference)
#include <cuda_runtime.h>
#include <cuda_bf16.h>
#include <cuda_fp16.h>
#include <stdint.h>

#define N_NODES 50000
#define N_EDGES 800000
#define ND 128
#define ED 64
#define HID 320

typedef uint32_t u32;

// ---------------- device globals (allocation-guard safe) -------------------
// P layout (fp16, 512 cols/node):
//   [0:256)   sender part:   quad q (dims 4q..4q+3): cols q*8+0..3 = val, q*8+4..7 = mul
//   [256:512) receiver part: same structure
__device__ __half g_Ph[(size_t)N_NODES * 512];
__device__ __half g_Wn[512 * 128];               // node weights fp16, rows = P cols
__device__ __half g_We[256 * 64];                // edge weights fp16 [j][k]

// ---------------- helpers ----------------------------------------------------
__device__ __forceinline__ u32 smem_u32(const void* p) {
    u32 a;
    asm("{ .reg .u64 t; cvta.to.shared.u64 t, %1; cvt.u32.u64 %0, t; }" : "=r"(a) : "l"(p));
    return a;
}
__device__ __forceinline__ void ldsm4(u32 addr, u32& r0, u32& r1, u32& r2, u32& r3) {
    asm volatile("ldmatrix.sync.aligned.m8n8.x4.shared.b16 {%0,%1,%2,%3}, [%4];"
                 : "=r"(r0), "=r"(r1), "=r"(r2), "=r"(r3) : "r"(addr));
}
__device__ __forceinline__ void ldsm2(u32 addr, u32& r0, u32& r1) {
    asm volatile("ldmatrix.sync.aligned.m8n8.x2.shared.b16 {%0,%1}, [%2];"
                 : "=r"(r0), "=r"(r1) : "r"(addr));
}
// fp32-acc fp16 MMA (node kernel)
__device__ __forceinline__ void mma16816h(float* d, u32 a0, u32 a1, u32 a2, u32 a3,
                                          u32 b0, u32 b1) {
    asm volatile(
        "mma.sync.aligned.m16n8k16.row.col.f32.f16.f16.f32 "
        "{%0,%1,%2,%3}, {%4,%5,%6,%7}, {%8,%9}, {%0,%1,%2,%3};"
        : "+f"(d[0]), "+f"(d[1]), "+f"(d[2]), "+f"(d[3])
        : "r"(a0), "r"(a1), "r"(a2), "r"(a3), "r"(b0), "r"(b1));
}
// fp16-acc fp16 MMA (edge kernel): D/C are 2 packed regs
__device__ __forceinline__ void mma16816hh(u32* d, u32 a0, u32 a1, u32 a2, u32 a3,
                                           u32 b0, u32 b1) {
    asm volatile(
        "mma.sync.aligned.m16n8k16.row.col.f16.f16.f16.f16 "
        "{%0,%1}, {%2,%3,%4,%5}, {%6,%7}, {%0,%1};"
        : "+r"(d[0]), "+r"(d[1])
        : "r"(a0), "r"(a1), "r"(a2), "r"(a3), "r"(b0), "r"(b1));
}
__device__ __forceinline__ void red4(float* p, float a, float b, float c, float d) {
    asm volatile("red.global.add.v4.f32 [%0], {%1,%2,%3,%4};"
                 :: "l"(p), "f"(a), "f"(b), "f"(c), "f"(d) : "memory");
}
__device__ __forceinline__ void split_f16(float v, __half& h, __half& l) {
    h = __float2half_rn(v);
    l = __float2half_rn(v - __half2float(h));
}
__device__ __forceinline__ float softplus_f(float x) {
    return fmaxf(x, 0.f) + __logf(1.f + __expf(-fabsf(x)));
}
__device__ __forceinline__ float sigmoid_f(float x) {
    return __fdividef(1.f, 1.f + __expf(-x));
}

// ---------------------------------------------------------------------------
// pack weights (interleaved Wn rows = P cols; We plain [j][k])
// ---------------------------------------------------------------------------
__global__ void pack_weights_kernel(const float* __restrict__ Wv,
                                    const float* __restrict__ Wm) {
    int i = blockIdx.x * blockDim.x + threadIdx.x;
    if (i < 512 * 128) {
        int p = i >> 7, k = i & 127;
        int half = p >> 8;
        int q = (p & 255) >> 3, t = p & 7;
        int d = q * 4 + (t & 3);
        const float* W = (t < 4) ? Wv : Wm;
        g_Wn[i] = __float2half_rn(W[d * HID + half * 128 + k]);
    }
    if (i < 256 * 64) {
        int j = i >> 6, k = i & 63;
        float v = (j < 128) ? Wv[j * HID + 256 + k] : Wm[(j - 128) * HID + 256 + k];
        g_We[i] = __float2half_rn(v);
    }
}

__global__ void zero_out_kernel(float4* __restrict__ out, int n4) {
    int i = blockIdx.x * blockDim.x + threadIdx.x;
    if (i < n4) out[i] = make_float4(0.f, 0.f, 0.f, 0.f);
}

// ---------------------------------------------------------------------------
// Node GEMM (fp16 A-split 2-term, fp32 acc): P = (Xh + Xl) @ Wn^T.
// tile 128 nodes x 256 j, 512 thr = 16 warps, warp = 16n x 128j. (unchanged)
// ---------------------------------------------------------------------------
#define NSTR 136
#define N_B  0
#define N_AH 69632
#define N_AL 104448
#define NODE_SMEM 139264

__global__ __launch_bounds__(512, 1) void node_gemm_kernel(const float* __restrict__ X) {
    extern __shared__ char smem[];
    u32 sb = smem_u32(smem);
    int tid = threadIdx.x, wid = tid >> 5, lane = tid & 31;
    int n0 = blockIdx.y * 256;

    {
        int j = tid >> 1, k0 = (tid & 1) * 64;
        #pragma unroll
        for (int c = 0; c < 64; c += 2) {
            __half2 h2;
            h2.x = g_Wn[(n0 + j) * 128 + k0 + c];
            h2.y = g_Wn[(n0 + j) * 128 + k0 + c + 1];
            *(__half2*)(smem + N_B + (j * NSTR + k0 + c) * 2) = h2;
        }
    }

    int egrp = wid >> 1, jgrp = wid & 1;
    u32 aH = sb + N_AH + ((egrp * 16 + (lane & 15)) * NSTR + (lane >> 4) * 8) * 2;
    u32 aL = sb + N_AL + ((egrp * 16 + (lane & 15)) * NSTR + (lane >> 4) * 8) * 2;
    u32 bB = sb + N_B + ((jgrp * 128 + (lane & 7)) * NSTR + (lane & 8)) * 2;

    const int ntiles = (N_NODES + 127) / 128;   // 391
    for (int t = blockIdx.x; t < ntiles; t += gridDim.x) {
        int m0 = t * 128;
        {
            int row = tid >> 2, k0 = (tid & 3) * 32;
            int gm = m0 + row;
            #pragma unroll
            for (int c = 0; c < 32; c += 2) {
                float2 xv = make_float2(0.f, 0.f);
                if (gm < N_NODES) xv = *(const float2*)&X[(size_t)gm * ND + k0 + c];
                __half h0, l0, h1, l1;
                split_f16(xv.x, h0, l0); split_f16(xv.y, h1, l1);
                *(__half2*)(smem + N_AH + (row * NSTR + k0 + c) * 2) = __half2(h0, h1);
                *(__half2*)(smem + N_AL + (row * NSTR + k0 + c) * 2) = __half2(l0, l1);
            }
        }
        __syncthreads();

        float acc[16][4];
        #pragma unroll
        for (int i = 0; i < 16; i++)
            #pragma unroll
            for (int j = 0; j < 4; j++) acc[i][j] = 0.f;

        #pragma unroll
        for (int kk = 0; kk < 8; kk++) {
            u32 ah0, ah1, ah2, ah3, al0, al1, al2, al3;
            ldsm4(aH + kk * 32, ah0, ah1, ah2, ah3);
            ldsm4(aL + kk * 32, al0, al1, al2, al3);
            #pragma unroll
            for (int nt = 0; nt < 16; nt++) {
                u32 b0, b1;
                ldsm2(bB + nt * (8 * NSTR * 2) + kk * 32, b0, b1);
                mma16816h(acc[nt], ah0, ah1, ah2, ah3, b0, b1);
                mma16816h(acc[nt], al0, al1, al2, al3, b0, b1);
            }
        }

        int nodeLo = m0 + egrp * 16 + (lane >> 2);
        int jbase = n0 + jgrp * 128 + (lane & 3) * 2;
        #pragma unroll
        for (int nt = 0; nt < 16; nt++) {
            if (nodeLo < N_NODES)
                *(__half2*)&g_Ph[(size_t)nodeLo * 512 + jbase + nt * 8] =
                    __floats2half2_rn(acc[nt][0], acc[nt][1]);
            if (nodeLo + 8 < N_NODES)
                *(__half2*)&g_Ph[(size_t)(nodeLo + 8) * 512 + jbase + nt * 8] =
                    __floats2half2_rn(acc[nt][2], acc[nt][3]);
        }
        __syncthreads();
    }
}

// ---------------------------------------------------------------------------
// Edge kernel v12: 128-edge tiles (2x), fp16 accumulators (keeps 32 acc regs),
// single-term fp16 MMA, paired 16B gathers, fill-epilogue overlap.
// Block 256 thr / 8 warps, 3 CTAs/SM. Warp = 64 edges (4 mt) x 16 dims.
// ---------------------------------------------------------------------------
#define EB_  0                      // 128 rows * 128B = 16384
#define EA_  16384                  // 128 rows * 128B = 16384 -> 32768
#define E_IDX 32768                 // 2 bufs * 256 ints -> 34816
#define EDGE_SMEM 34816

__global__ __launch_bounds__(256, 3) void edge_kernel(
    const float* __restrict__ ef, const int* __restrict__ ei,
    const float* __restrict__ b_val, const float* __restrict__ b_mul,
    float* __restrict__ out)
{
    extern __shared__ char smem[];
    u32 sb = smem_u32(smem);
    int tid = threadIdx.x, wid = tid >> 5, lane = tid & 31;
    int jhalf = blockIdx.y;
    int* idxb = (int*)(smem + E_IDX);   // [buf][256]: s at +0, r at +128

    // ---- B fill (once): permuted rows, xor-swizzled, single fp16 ----
    {
        int jl = tid >> 1, k0 = (tid & 1) * 32;
        int jgrp_ = jl >> 5, jj = jl & 31, ntb = jj >> 3, rr = jj & 7;
        int dd = (rr >> 1) * 4 + (ntb & 1) * 2 + (rr & 1);
        int jg = ((ntb < 2) ? 0 : 128) + jhalf * 64 + jgrp_ * 16 + dd;
        int xorm = (jl & 7) << 4;
        #pragma unroll
        for (int c = 0; c < 32; c += 2) {
            u32 off = (u32)(jl * 128) + (u32)(((k0 + c) * 2) ^ xorm);
            __half2 h2;
            h2.x = g_We[jg * 64 + k0 + c]; h2.y = g_We[jg * 64 + k0 + c + 1];
            *(__half2*)(smem + EB_ + off) = h2;
        }
    }

    int egrp = wid >> 2, jgrp = wid & 3;   // egrp: 64-edge half; jgrp: 16 dims

    int jrow = jgrp * 32 + ((lane >> 4) & 1) * 8 + (lane & 7);
    u32 bRow = sb + EB_ + (u32)(jrow * 128);
    int bxor = (jrow & 7) << 4;
    int bk16 = ((lane >> 3) & 1) * 16;

    u32 aRow = sb + EA_ + (u32)((lane & 15) * 128);
    int axor = (lane & 7) << 4;
    int ak16 = (lane >> 4) * 16;

    int q = lane & 3;
    int dbase = jhalf * 64 + jgrp * 16 + q * 4;
    int dq8 = (dbase >> 2) * 8;             // paired P offset (halfs)
    const float4 bv4 = *(const float4*)&b_val[dbase];
    const float4 bm4 = *(const float4*)&b_mul[dbase];

    // A-fill lane mapping: thread -> (edge row, 32-k half-row)
    int fe = tid >> 1, fk0 = (tid & 1) * 32;
    int fxm = (fe & 7) << 4;

    const int stride = gridDim.x;
    const int ntiles = N_EDGES / 128;   // 6250
    int tile = blockIdx.x;

    // ---- prologue: fill A + idx for first tile ----
    if (tile < ntiles) {
        int e0 = tile * 128;
        if (tid < 128) idxb[tid] = ei[e0 + tid];
        else           idxb[tid] = ei[N_EDGES + e0 + tid - 128];
        const float4* src4 = (const float4*)&ef[(size_t)(e0 + fe) * ED + fk0];
        #pragma unroll
        for (int c = 0; c < 32; c += 4) {
            float4 xv = src4[c >> 2];
            __half2 h01 = __floats2half2_rn(xv.x, xv.y);
            __half2 h23 = __floats2half2_rn(xv.z, xv.w);
            u32 off = (u32)(fe * 128) + (u32)(((fk0 + c) * 2) ^ fxm);
            *(uint2*)(smem + EA_ + off) = make_uint2(*(u32*)&h01, *(u32*)&h23);
        }
    }
    __syncthreads();

    int buf = 0;
    for (; tile < ntiles; tile += stride) {
        // ---- MMA: fp16 accumulators, B shared across 4 mt slices ----
        u32 acc[4][4][2];
        #pragma unroll
        for (int mt = 0; mt < 4; mt++)
            #pragma unroll
            for (int nt = 0; nt < 4; nt++) {
                acc[mt][nt][0] = 0u; acc[mt][nt][1] = 0u;
            }

        #pragma unroll
        for (int kk = 0; kk < 4; kk++) {
            u32 akx = (u32)((kk * 32 + ak16) ^ axor);
            u32 bkx = (u32)((kk * 32 + bk16) ^ bxor);
            u32 b00, b01, b02, b03, b10, b11, b12, b13;
            ldsm4(bRow + bkx, b00, b01, b02, b03);
            ldsm4(bRow + 2048 + bkx, b10, b11, b12, b13);
            #pragma unroll
            for (int mt = 0; mt < 4; mt++) {
                u32 a0, a1, a2, a3;
                ldsm4(aRow + (u32)((egrp * 64 + mt * 16) * 128) + akx, a0, a1, a2, a3);
                mma16816hh(acc[mt][0], a0, a1, a2, a3, b00, b01);
                mma16816hh(acc[mt][1], a0, a1, a2, a3, b02, b03);
                mma16816hh(acc[mt][2], a0, a1, a2, a3, b10, b11);
                mma16816hh(acc[mt][3], a0, a1, a2, a3, b12, b13);
            }
        }
        __syncthreads();   // A smem consumed; safe to refill

        // ---- overlap: next tile's A fill + idx loads BEFORE epilogue ----
        int nxt = tile + stride;
        if (nxt < ntiles) {
            int e0n = nxt * 128;
            int* nb = idxb + (buf ^ 1) * 256;
            if (tid < 128) nb[tid] = ei[e0n + tid];
            else           nb[tid] = ei[N_EDGES + e0n + tid - 128];
            const float4* src4 = (const float4*)&ef[(size_t)(e0n + fe) * ED + fk0];
            #pragma unroll
            for (int c = 0; c < 32; c += 4) {
                float4 xv = src4[c >> 2];
                __half2 h01 = __floats2half2_rn(xv.x, xv.y);
                __half2 h23 = __floats2half2_rn(xv.z, xv.w);
                u32 off = (u32)(fe * 128) + (u32)(((fk0 + c) * 2) ^ fxm);
                *(uint2*)(smem + EA_ + off) = make_uint2(*(u32*)&h01, *(u32*)&h23);
            }
        }

        // ---- register epilogue: paired 16B P gathers + red.v4 scatter ----
        const int* cb = idxb + buf * 256;
        #pragma unroll
        for (int mt = 0; mt < 4; mt++) {
            #pragma unroll
            for (int h = 0; h < 2; h++) {
                int e = egrp * 64 + mt * 16 + h * 8 + (lane >> 2);
                int s = cb[e];
                int r = cb[128 + e];
                uint4 us = *(const uint4*)&g_Ph[(size_t)s * 512 + dq8];
                uint4 ur = *(const uint4*)&g_Ph[(size_t)r * 512 + 256 + dq8];
                float2 sv01 = __half22float2(*(__half2*)&us.x);
                float2 sv23 = __half22float2(*(__half2*)&us.y);
                float2 sm01 = __half22float2(*(__half2*)&us.z);
                float2 sm23 = __half22float2(*(__half2*)&us.w);
                float2 rv01 = __half22float2(*(__half2*)&ur.x);
                float2 rv23 = __half22float2(*(__half2*)&ur.y);
                float2 rm01 = __half22float2(*(__half2*)&ur.z);
                float2 rm23 = __half22float2(*(__half2*)&ur.w);

                float2 qv01 = __half22float2(*(__half2*)&acc[mt][0][h]);
                float2 qv23 = __half22float2(*(__half2*)&acc[mt][1][h]);
                float2 qm01 = __half22float2(*(__half2*)&acc[mt][2][h]);
                float2 qm23 = __half22float2(*(__half2*)&acc[mt][3][h]);

                float v0 = qv01.x + sv01.x + rv01.x + bv4.x;
                float v1 = qv01.y + sv01.y + rv01.y + bv4.y;
                float v2 = qv23.x + sv23.x + rv23.x + bv4.z;
                float v3 = qv23.y + sv23.y + rv23.y + bv4.w;
                float m0 = qm01.x + sm01.x + rm01.x + bm4.x;
                float m1 = qm01.y + sm01.y + rm01.y + bm4.y;
                float m2 = qm23.x + sm23.x + rm23.x + bm4.z;
                float m3 = qm23.y + sm23.y + rm23.y + bm4.w;

                float g0 = softplus_f(v0) * sigmoid_f(m0);
                float g1 = softplus_f(v1) * sigmoid_f(m1);
                float g2 = softplus_f(v2) * sigmoid_f(m2);
                float g3 = softplus_f(v3) * sigmoid_f(m3);

                red4(out + (size_t)r * ND + dbase, g0, g1, g2, g3);
            }
        }
        __syncthreads();   // next tile's A fill complete before its MMA
        buf ^= 1;
    }
}

// ---------------------------------------------------------------------------
extern "C" void kernel_launch(void* const* d_in, const int* in_sizes, int n_in,
                              void* d_out, int out_size) {
    const float* x  = (const float*)d_in[0];
    const int*   ei = (const int*)  d_in[1];
    const float* ef = (const float*)d_in[2];
    const float* Wv = (const float*)d_in[3];
    const float* bv = (const float*)d_in[4];
    const float* Wm = (const float*)d_in[5];
    const float* bm = (const float*)d_in[6];
    float* out = (float*)d_out;

    cudaFuncSetAttribute(node_gemm_kernel,
                         cudaFuncAttributeMaxDynamicSharedMemorySize, NODE_SMEM);
    cudaFuncSetAttribute(edge_kernel,
                         cudaFuncAttributeMaxDynamicSharedMemorySize, EDGE_SMEM);

    pack_weights_kernel<<<256, 256>>>(Wv, Wm);

    int n4 = N_NODES * ND / 4;
    zero_out_kernel<<<(n4 + 255) / 256, 256>>>((float4*)out, n4);

    node_gemm_kernel<<<dim3(74, 2), 512, NODE_SMEM>>>(x);

    edge_kernel<<<dim3(222, 2), 256, EDGE_SMEM>>>(ef, ei, bv, bm, out);
}

// round 14
// speedup vs baseline: 1.0205x; 1.0205x over previous
#include <cuda_runtime.h>
#include <cuda_bf16.h>
#include <cuda_fp16.h>
#include <stdint.h>

#define N_NODES 50000
#define N_EDGES 800000
#define ND 128
#define ED 64
#define HID 320

typedef uint32_t u32;

// ---------------- device globals (allocation-guard safe) -------------------
// P layout (fp16, 512 cols/node):
//   [0:256)   sender part:   quad q (dims 4q..4q+3): cols q*8+0..3 = val, q*8+4..7 = mul
//   [256:512) receiver part: same structure
__device__ __half g_Ph[(size_t)N_NODES * 512];
__device__ __half g_Wn[512 * 128];               // node weights fp16, rows = P cols
__device__ __half g_We[256 * 64];                // edge weights fp16 [j][k]

// ---------------- helpers ----------------------------------------------------
__device__ __forceinline__ u32 smem_u32(const void* p) {
    u32 a;
    asm("{ .reg .u64 t; cvta.to.shared.u64 t, %1; cvt.u32.u64 %0, t; }" : "=r"(a) : "l"(p));
    return a;
}
__device__ __forceinline__ void ldsm4(u32 addr, u32& r0, u32& r1, u32& r2, u32& r3) {
    asm volatile("ldmatrix.sync.aligned.m8n8.x4.shared.b16 {%0,%1,%2,%3}, [%4];"
                 : "=r"(r0), "=r"(r1), "=r"(r2), "=r"(r3) : "r"(addr));
}
__device__ __forceinline__ void mma16816h(float* d, u32 a0, u32 a1, u32 a2, u32 a3,
                                          u32 b0, u32 b1) {
    asm volatile(
        "mma.sync.aligned.m16n8k16.row.col.f32.f16.f16.f32 "
        "{%0,%1,%2,%3}, {%4,%5,%6,%7}, {%8,%9}, {%0,%1,%2,%3};"
        : "+f"(d[0]), "+f"(d[1]), "+f"(d[2]), "+f"(d[3])
        : "r"(a0), "r"(a1), "r"(a2), "r"(a3), "r"(b0), "r"(b1));
}
__device__ __forceinline__ void red4(float* p, float a, float b, float c, float d) {
    asm volatile("red.global.add.v4.f32 [%0], {%1,%2,%3,%4};"
                 :: "l"(p), "f"(a), "f"(b), "f"(c), "f"(d) : "memory");
}
__device__ __forceinline__ void split_f16(float v, __half& h, __half& l) {
    h = __float2half_rn(v);
    l = __float2half_rn(v - __half2float(h));
}
__device__ __forceinline__ float softplus_f(float x) {
    return fmaxf(x, 0.f) + __logf(1.f + __expf(-fabsf(x)));
}
__device__ __forceinline__ float sigmoid_f(float x) {
    return __fdividef(1.f, 1.f + __expf(-x));
}

// ---------------------------------------------------------------------------
// pack weights (interleaved Wn rows = P cols; We plain [j][k])
// ---------------------------------------------------------------------------
__global__ void pack_weights_kernel(const float* __restrict__ Wv,
                                    const float* __restrict__ Wm) {
    int i = blockIdx.x * blockDim.x + threadIdx.x;
    if (i < 512 * 128) {
        int p = i >> 7, k = i & 127;
        int half = p >> 8;
        int q = (p & 255) >> 3, t = p & 7;
        int d = q * 4 + (t & 3);
        const float* W = (t < 4) ? Wv : Wm;
        g_Wn[i] = __float2half_rn(W[d * HID + half * 128 + k]);
    }
    if (i < 256 * 64) {
        int j = i >> 6, k = i & 63;
        float v = (j < 128) ? Wv[j * HID + 256 + k] : Wm[(j - 128) * HID + 256 + k];
        g_We[i] = __float2half_rn(v);
    }
}

__global__ void zero_out_kernel(float4* __restrict__ out, int n4) {
    int i = blockIdx.x * blockDim.x + threadIdx.x;
    if (i < n4) out[i] = make_float4(0.f, 0.f, 0.f, 0.f);
}

// ---------------------------------------------------------------------------
// Node GEMM v13 (fp16 A-split 2-term, fp32 acc): P = (Xh + Xl) @ Wn^T.
// Tile 64 nodes x 256 j, 256 thr / 8 warps, 2 CTAs/SM.
// Warp = 16 nodes (egrp=wid>>1) x 128 j (jgrp=wid&1, nt=16, ldsm4 B pairs).
// ---------------------------------------------------------------------------
#define NSTR 136
#define N_B  0                      // 256*136*2 = 69632
#define N_AH 69632                  // 64*136*2 = 17408
#define N_AL 87040                  // -> 104448
#define NODE_SMEM 104448

__global__ __launch_bounds__(256, 2) void node_gemm_kernel(const float* __restrict__ X) {
    extern __shared__ char smem[];
    u32 sb = smem_u32(smem);
    int tid = threadIdx.x, wid = tid >> 5, lane = tid & 31;
    int n0 = blockIdx.y * 256;

    // B fill (Wn half [256 j][128 k]) fp16, padded rows — once per CTA
    {
        int j = tid;
        #pragma unroll
        for (int c = 0; c < 128; c += 2) {
            __half2 h2;
            h2.x = g_Wn[(n0 + j) * 128 + c];
            h2.y = g_Wn[(n0 + j) * 128 + c + 1];
            *(__half2*)(smem + N_B + (j * NSTR + c) * 2) = h2;
        }
    }

    int egrp = wid >> 1, jgrp = wid & 1;
    u32 aH = sb + N_AH + ((egrp * 16 + (lane & 15)) * NSTR + (lane >> 4) * 8) * 2;
    u32 aL = sb + N_AL + ((egrp * 16 + (lane & 15)) * NSTR + (lane >> 4) * 8) * 2;
    u32 bB = sb + N_B + ((jgrp * 128 + ((lane >> 4) & 1) * 8 + (lane & 7)) * NSTR) * 2
                 + ((lane >> 3) & 1) * 16;

    const int ntiles = (N_NODES + 63) / 64;   // 782
    for (int t = blockIdx.x; t < ntiles; t += gridDim.x) {
        int m0 = t * 64;
        {
            int row = tid >> 2, k0 = (tid & 3) * 32;
            int gm = m0 + row;
            #pragma unroll
            for (int c = 0; c < 32; c += 2) {
                float2 xv = make_float2(0.f, 0.f);
                if (gm < N_NODES) xv = *(const float2*)&X[(size_t)gm * ND + k0 + c];
                __half h0, l0, h1, l1;
                split_f16(xv.x, h0, l0); split_f16(xv.y, h1, l1);
                *(__half2*)(smem + N_AH + (row * NSTR + k0 + c) * 2) = __half2(h0, h1);
                *(__half2*)(smem + N_AL + (row * NSTR + k0 + c) * 2) = __half2(l0, l1);
            }
        }
        __syncthreads();

        float acc[16][4];
        #pragma unroll
        for (int i = 0; i < 16; i++)
            #pragma unroll
            for (int j = 0; j < 4; j++) acc[i][j] = 0.f;

        #pragma unroll
        for (int kk = 0; kk < 8; kk++) {
            u32 ah0, ah1, ah2, ah3, al0, al1, al2, al3;
            ldsm4(aH + kk * 32, ah0, ah1, ah2, ah3);
            ldsm4(aL + kk * 32, al0, al1, al2, al3);
            #pragma unroll
            for (int np = 0; np < 8; np++) {
                u32 b0, b1, b2, b3;
                ldsm4(bB + np * (16 * NSTR * 2) + kk * 32, b0, b1, b2, b3);
                mma16816h(acc[np * 2 + 0], ah0, ah1, ah2, ah3, b0, b1);
                mma16816h(acc[np * 2 + 0], al0, al1, al2, al3, b0, b1);
                mma16816h(acc[np * 2 + 1], ah0, ah1, ah2, ah3, b2, b3);
                mma16816h(acc[np * 2 + 1], al0, al1, al2, al3, b2, b3);
            }
        }

        int nodeLo = m0 + egrp * 16 + (lane >> 2);
        int jbase = n0 + jgrp * 128 + (lane & 3) * 2;
        #pragma unroll
        for (int nt = 0; nt < 16; nt++) {
            if (nodeLo < N_NODES)
                *(__half2*)&g_Ph[(size_t)nodeLo * 512 + jbase + nt * 8] =
                    __floats2half2_rn(acc[nt][0], acc[nt][1]);
            if (nodeLo + 8 < N_NODES)
                *(__half2*)&g_Ph[(size_t)(nodeLo + 8) * 512 + jbase + nt * 8] =
                    __floats2half2_rn(acc[nt][2], acc[nt][3]);
        }
        __syncthreads();
    }
}

// ---------------------------------------------------------------------------
// Edge kernel v11 (reverted verbatim — known 286 us):
// single-term fp16 MMA, paired 16B P gathers, float4 A-fill with 8B swizzled
// stores, fill-epilogue overlap. 256 thr / 8 warps, 3 CTAs/SM.
// Tile 64 edges x 128 j (jhalf class).
// ---------------------------------------------------------------------------
#define EB_  0                      // 128 rows * 128B = 16384
#define EA_  16384                  // 64 rows * 128B = 8192 -> 24576
#define E_IDX 24576                 // 2 bufs * 128 ints -> 25600
#define EDGE_SMEM 25600

__global__ __launch_bounds__(256, 3) void edge_kernel(
    const float* __restrict__ ef, const int* __restrict__ ei,
    const float* __restrict__ b_val, const float* __restrict__ b_mul,
    float* __restrict__ out)
{
    extern __shared__ char smem[];
    u32 sb = smem_u32(smem);
    int tid = threadIdx.x, wid = tid >> 5, lane = tid & 31;
    int jhalf = blockIdx.y;
    int* idxb = (int*)(smem + E_IDX);   // [buf][128]: s at +0, r at +64

    // ---- B fill (once): permuted rows, xor-swizzled, single fp16 ----
    {
        int jl = tid >> 1, k0 = (tid & 1) * 32;
        int jgrp_ = jl >> 5, jj = jl & 31, ntb = jj >> 3, rr = jj & 7;
        int dd = (rr >> 1) * 4 + (ntb & 1) * 2 + (rr & 1);
        int jg = ((ntb < 2) ? 0 : 128) + jhalf * 64 + jgrp_ * 16 + dd;
        int xorm = (jl & 7) << 4;
        #pragma unroll
        for (int c = 0; c < 32; c += 2) {
            u32 off = (u32)(jl * 128) + (u32)(((k0 + c) * 2) ^ xorm);
            __half2 h2;
            h2.x = g_We[jg * 64 + k0 + c]; h2.y = g_We[jg * 64 + k0 + c + 1];
            *(__half2*)(smem + EB_ + off) = h2;
        }
    }

    int egrp = wid >> 2, jgrp = wid & 3;

    int jrow = jgrp * 32 + ((lane >> 4) & 1) * 8 + (lane & 7);
    u32 bRow = sb + EB_ + (u32)(jrow * 128);
    int bxor = (jrow & 7) << 4;
    int bk16 = ((lane >> 3) & 1) * 16;

    u32 aRow = sb + EA_ + (u32)((lane & 15) * 128);
    int axor = (lane & 7) << 4;
    int ak16 = (lane >> 4) * 16;

    int q = lane & 3;
    int dbase = jhalf * 64 + jgrp * 16 + q * 4;
    int dq8 = (dbase >> 2) * 8;             // paired P offset (halfs)
    const float4 bv4 = *(const float4*)&b_val[dbase];
    const float4 bm4 = *(const float4*)&b_mul[dbase];

    // A-fill lane mapping (constant)
    int fe = tid >> 2, fk0 = (tid & 3) * 16;
    int fxm = (fe & 7) << 4;

    const int stride = gridDim.x;
    const int ntiles = N_EDGES / 64;   // 12500
    int tile = blockIdx.x;

    // ---- prologue: fill A + idx for first tile ----
    if (tile < ntiles) {
        int e0 = tile * 64;
        if (tid < 64)       idxb[tid] = ei[e0 + tid];
        else if (tid < 128) idxb[tid] = ei[N_EDGES + e0 + tid - 64];
        const float4* src4 = (const float4*)&ef[(size_t)(e0 + fe) * ED + fk0];
        #pragma unroll
        for (int c = 0; c < 16; c += 4) {
            float4 xv = src4[c >> 2];
            __half2 h01 = __floats2half2_rn(xv.x, xv.y);
            __half2 h23 = __floats2half2_rn(xv.z, xv.w);
            u32 off = (u32)(fe * 128) + (u32)(((fk0 + c) * 2) ^ fxm);
            *(uint2*)(smem + EA_ + off) =
                make_uint2(*(u32*)&h01, *(u32*)&h23);
        }
    }
    __syncthreads();

    int buf = 0;
    for (; tile < ntiles; tile += stride) {
        float acc[2][4][4];
        #pragma unroll
        for (int mt = 0; mt < 2; mt++)
            #pragma unroll
            for (int nt = 0; nt < 4; nt++)
                #pragma unroll
                for (int j = 0; j < 4; j++) acc[mt][nt][j] = 0.f;

        #pragma unroll
        for (int kk = 0; kk < 4; kk++) {
            u32 akx = (u32)((kk * 32 + ak16) ^ axor);
            u32 p0, p1, p2, p3, q0, q1, q2, q3;
            ldsm4(aRow + (u32)((egrp * 32) * 128) + akx, p0, p1, p2, p3);
            ldsm4(aRow + (u32)((egrp * 32 + 16) * 128) + akx, q0, q1, q2, q3);
            u32 bkx = (u32)((kk * 32 + bk16) ^ bxor);
            #pragma unroll
            for (int np = 0; np < 2; np++) {
                u32 b0, b1, b2, b3;
                ldsm4(bRow + np * 2048 + bkx, b0, b1, b2, b3);
                mma16816h(acc[0][np * 2 + 0], p0, p1, p2, p3, b0, b1);
                mma16816h(acc[0][np * 2 + 1], p0, p1, p2, p3, b2, b3);
                mma16816h(acc[1][np * 2 + 0], q0, q1, q2, q3, b0, b1);
                mma16816h(acc[1][np * 2 + 1], q0, q1, q2, q3, b2, b3);
            }
        }
        __syncthreads();   // A smem consumed; safe to refill

        // ---- overlap: issue next tile's A fill + idx loads BEFORE epilogue ----
        int nxt = tile + stride;
        if (nxt < ntiles) {
            int e0n = nxt * 64;
            int* nb = idxb + (buf ^ 1) * 128;
            if (tid < 64)       nb[tid] = ei[e0n + tid];
            else if (tid < 128) nb[tid] = ei[N_EDGES + e0n + tid - 64];
            const float4* src4 = (const float4*)&ef[(size_t)(e0n + fe) * ED + fk0];
            #pragma unroll
            for (int c = 0; c < 16; c += 4) {
                float4 xv = src4[c >> 2];
                __half2 h01 = __floats2half2_rn(xv.x, xv.y);
                __half2 h23 = __floats2half2_rn(xv.z, xv.w);
                u32 off = (u32)(fe * 128) + (u32)(((fk0 + c) * 2) ^ fxm);
                *(uint2*)(smem + EA_ + off) =
                    make_uint2(*(u32*)&h01, *(u32*)&h23);
            }
        }

        // ---- register epilogue: paired 16B P gathers + red.v4 scatter ----
        const int* cb = idxb + buf * 128;
        #pragma unroll
        for (int mt = 0; mt < 2; mt++) {
            #pragma unroll
            for (int h = 0; h < 2; h++) {
                int e = egrp * 32 + mt * 16 + h * 8 + (lane >> 2);
                int s = cb[e];
                int r = cb[64 + e];
                uint4 us = *(const uint4*)&g_Ph[(size_t)s * 512 + dq8];
                uint4 ur = *(const uint4*)&g_Ph[(size_t)r * 512 + 256 + dq8];
                float2 sv01 = __half22float2(*(__half2*)&us.x);
                float2 sv23 = __half22float2(*(__half2*)&us.y);
                float2 sm01 = __half22float2(*(__half2*)&us.z);
                float2 sm23 = __half22float2(*(__half2*)&us.w);
                float2 rv01 = __half22float2(*(__half2*)&ur.x);
                float2 rv23 = __half22float2(*(__half2*)&ur.y);
                float2 rm01 = __half22float2(*(__half2*)&ur.z);
                float2 rm23 = __half22float2(*(__half2*)&ur.w);

                float v0 = acc[mt][0][2 * h + 0] + sv01.x + rv01.x + bv4.x;
                float v1 = acc[mt][0][2 * h + 1] + sv01.y + rv01.y + bv4.y;
                float v2 = acc[mt][1][2 * h + 0] + sv23.x + rv23.x + bv4.z;
                float v3 = acc[mt][1][2 * h + 1] + sv23.y + rv23.y + bv4.w;
                float m0 = acc[mt][2][2 * h + 0] + sm01.x + rm01.x + bm4.x;
                float m1 = acc[mt][2][2 * h + 1] + sm01.y + rm01.y + bm4.y;
                float m2 = acc[mt][3][2 * h + 0] + sm23.x + rm23.x + bm4.z;
                float m3 = acc[mt][3][2 * h + 1] + sm23.y + rm23.y + bm4.w;

                float g0 = softplus_f(v0) * sigmoid_f(m0);
                float g1 = softplus_f(v1) * sigmoid_f(m1);
                float g2 = softplus_f(v2) * sigmoid_f(m2);
                float g3 = softplus_f(v3) * sigmoid_f(m3);

                red4(out + (size_t)r * ND + dbase, g0, g1, g2, g3);
            }
        }
        __syncthreads();   // next tile's A fill complete before its MMA
        buf ^= 1;
    }
}

// ---------------------------------------------------------------------------
extern "C" void kernel_launch(void* const* d_in, const int* in_sizes, int n_in,
                              void* d_out, int out_size) {
    const float* x  = (const float*)d_in[0];
    const int*   ei = (const int*)  d_in[1];
    const float* ef = (const float*)d_in[2];
    const float* Wv = (const float*)d_in[3];
    const float* bv = (const float*)d_in[4];
    const float* Wm = (const float*)d_in[5];
    const float* bm = (const float*)d_in[6];
    float* out = (float*)d_out;

    cudaFuncSetAttribute(node_gemm_kernel,
                         cudaFuncAttributeMaxDynamicSharedMemorySize, NODE_SMEM);
    cudaFuncSetAttribute(edge_kernel,
                         cudaFuncAttributeMaxDynamicSharedMemorySize, EDGE_SMEM);

    pack_weights_kernel<<<256, 256>>>(Wv, Wm);

    int n4 = N_NODES * ND / 4;
    zero_out_kernel<<<(n4 + 255) / 256, 256>>>((float4*)out, n4);

    node_gemm_kernel<<<dim3(148, 2), 256, NODE_SMEM>>>(x);

    edge_kernel<<<dim3(222, 2), 256, EDGE_SMEM>>>(ef, ei, bv, bm, out);
}

// round 15
// speedup vs baseline: 1.1470x; 1.1240x over previous
#include <cuda_runtime.h>
#include <cuda_bf16.h>
#include <cuda_fp16.h>
#include <stdint.h>

#define N_NODES 50000
#define N_EDGES 800000
#define ND 128
#define ED 64
#define HID 320

typedef uint32_t u32;

// ---------------- device globals (allocation-guard safe) -------------------
// P layout (fp16, 512 cols/node):
//   [0:256)   sender part:   quad q (dims 4q..4q+3): cols q*8+0..3 = val, q*8+4..7 = mul
//   [256:512) receiver part: same structure
__device__ __half g_Ph[(size_t)N_NODES * 512];
__device__ __half g_Wn[512 * 128];               // node weights fp16, rows = P cols
__device__ __half g_We[256 * 64];                // edge weights fp16 [j][k]

// ---------------- helpers ----------------------------------------------------
__device__ __forceinline__ u32 smem_u32(const void* p) {
    u32 a;
    asm("{ .reg .u64 t; cvta.to.shared.u64 t, %1; cvt.u32.u64 %0, t; }" : "=r"(a) : "l"(p));
    return a;
}
__device__ __forceinline__ void ldsm4(u32 addr, u32& r0, u32& r1, u32& r2, u32& r3) {
    asm volatile("ldmatrix.sync.aligned.m8n8.x4.shared.b16 {%0,%1,%2,%3}, [%4];"
                 : "=r"(r0), "=r"(r1), "=r"(r2), "=r"(r3) : "r"(addr));
}
__device__ __forceinline__ void mma16816h(float* d, u32 a0, u32 a1, u32 a2, u32 a3,
                                          u32 b0, u32 b1) {
    asm volatile(
        "mma.sync.aligned.m16n8k16.row.col.f32.f16.f16.f32 "
        "{%0,%1,%2,%3}, {%4,%5,%6,%7}, {%8,%9}, {%0,%1,%2,%3};"
        : "+f"(d[0]), "+f"(d[1]), "+f"(d[2]), "+f"(d[3])
        : "r"(a0), "r"(a1), "r"(a2), "r"(a3), "r"(b0), "r"(b1));
}
__device__ __forceinline__ void red4(float* p, float a, float b, float c, float d) {
    asm volatile("red.global.add.v4.f32 [%0], {%1,%2,%3,%4};"
                 :: "l"(p), "f"(a), "f"(b), "f"(c), "f"(d) : "memory");
}
__device__ __forceinline__ float softplus_f(float x) {
    return fmaxf(x, 0.f) + __logf(1.f + __expf(-fabsf(x)));
}
__device__ __forceinline__ float sigmoid_f(float x) {
    return __fdividef(1.f, 1.f + __expf(-x));
}

// ---------------------------------------------------------------------------
// prep: zero output + pack weights (fused, one launch)
// ---------------------------------------------------------------------------
__global__ void prep_kernel(const float* __restrict__ Wv,
                            const float* __restrict__ Wm,
                            float4* __restrict__ out, int n4) {
    int i = blockIdx.x * blockDim.x + threadIdx.x;
    if (i < n4) out[i] = make_float4(0.f, 0.f, 0.f, 0.f);
    if (i < 512 * 128) {
        int p = i >> 7, k = i & 127;
        int half = p >> 8;
        int q = (p & 255) >> 3, t = p & 7;
        int d = q * 4 + (t & 3);
        const float* W = (t < 4) ? Wv : Wm;
        g_Wn[i] = __float2half_rn(W[d * HID + half * 128 + k]);
    }
    if (i < 256 * 64) {
        int j = i >> 6, k = i & 63;
        float v = (j < 128) ? Wv[j * HID + 256 + k] : Wm[(j - 128) * HID + 256 + k];
        g_We[i] = __float2half_rn(v);
    }
}

// ---------------------------------------------------------------------------
// Node GEMM v14 (single fp16 term): P = Xh @ Wn^T.
// Tile 128 nodes x 256 j, 512 thr / 16 warps, warp = 16n x 128j.
// B fragments via ldsm4 pairs (R13-verified mapping).
// ---------------------------------------------------------------------------
#define NSTR 136
#define N_B  0                      // 256*136*2 = 69632
#define N_A  69632                  // 128*136*2 = 34816 -> 104448
#define NODE_SMEM 104448

__global__ __launch_bounds__(512, 1) void node_gemm_kernel(const float* __restrict__ X) {
    extern __shared__ char smem[];
    u32 sb = smem_u32(smem);
    int tid = threadIdx.x, wid = tid >> 5, lane = tid & 31;
    int n0 = blockIdx.y * 256;

    // B fill (Wn half [256 j][128 k]) fp16, padded rows
    {
        int j = tid >> 1, k0 = (tid & 1) * 64;
        #pragma unroll
        for (int c = 0; c < 64; c += 2) {
            __half2 h2;
            h2.x = g_Wn[(n0 + j) * 128 + k0 + c];
            h2.y = g_Wn[(n0 + j) * 128 + k0 + c + 1];
            *(__half2*)(smem + N_B + (j * NSTR + k0 + c) * 2) = h2;
        }
    }

    int egrp = wid >> 1, jgrp = wid & 1;
    u32 aA = sb + N_A + ((egrp * 16 + (lane & 15)) * NSTR + (lane >> 4) * 8) * 2;
    // ldsm4 B: rows jgrp*128 + np*16 + ((lane>>4)&1)*8 + (lane&7); k-half (lane>>3)&1
    u32 bB = sb + N_B + ((jgrp * 128 + ((lane >> 4) & 1) * 8 + (lane & 7)) * NSTR) * 2
                 + ((lane >> 3) & 1) * 16;

    const int ntiles = (N_NODES + 127) / 128;   // 391
    for (int t = blockIdx.x; t < ntiles; t += gridDim.x) {
        int m0 = t * 128;
        // A fill (X tile [128][128]) single fp16
        {
            int row = tid >> 2, k0 = (tid & 3) * 32;
            int gm = m0 + row;
            #pragma unroll
            for (int c = 0; c < 32; c += 4) {
                float4 xv = make_float4(0.f, 0.f, 0.f, 0.f);
                if (gm < N_NODES) xv = *(const float4*)&X[(size_t)gm * ND + k0 + c];
                __half2 h01 = __floats2half2_rn(xv.x, xv.y);
                __half2 h23 = __floats2half2_rn(xv.z, xv.w);
                *(uint2*)(smem + N_A + (row * NSTR + k0 + c) * 2) =
                    make_uint2(*(u32*)&h01, *(u32*)&h23);
            }
        }
        __syncthreads();

        float acc[16][4];
        #pragma unroll
        for (int i = 0; i < 16; i++)
            #pragma unroll
            for (int j = 0; j < 4; j++) acc[i][j] = 0.f;

        #pragma unroll
        for (int kk = 0; kk < 8; kk++) {
            u32 a0, a1, a2, a3;
            ldsm4(aA + kk * 32, a0, a1, a2, a3);
            #pragma unroll
            for (int np = 0; np < 8; np++) {
                u32 b0, b1, b2, b3;
                ldsm4(bB + np * (16 * NSTR * 2) + kk * 32, b0, b1, b2, b3);
                mma16816h(acc[np * 2 + 0], a0, a1, a2, a3, b0, b1);
                mma16816h(acc[np * 2 + 1], a0, a1, a2, a3, b2, b3);
            }
        }

        int nodeLo = m0 + egrp * 16 + (lane >> 2);
        int jbase = n0 + jgrp * 128 + (lane & 3) * 2;
        #pragma unroll
        for (int nt = 0; nt < 16; nt++) {
            if (nodeLo < N_NODES)
                *(__half2*)&g_Ph[(size_t)nodeLo * 512 + jbase + nt * 8] =
                    __floats2half2_rn(acc[nt][0], acc[nt][1]);
            if (nodeLo + 8 < N_NODES)
                *(__half2*)&g_Ph[(size_t)(nodeLo + 8) * 512 + jbase + nt * 8] =
                    __floats2half2_rn(acc[nt][2], acc[nt][3]);
        }
        __syncthreads();
    }
}

// ---------------------------------------------------------------------------
// Edge kernel v11 (unchanged — measured 285 us):
// single-term fp16 MMA, paired 16B P gathers, float4 A-fill with 8B swizzled
// stores, fill-epilogue overlap. 256 thr / 8 warps, 3 CTAs/SM.
// Tile 64 edges x 128 j (jhalf class).
// ---------------------------------------------------------------------------
#define EB_  0                      // 128 rows * 128B = 16384
#define EA_  16384                  // 64 rows * 128B = 8192 -> 24576
#define E_IDX 24576                 // 2 bufs * 128 ints -> 25600
#define EDGE_SMEM 25600

__global__ __launch_bounds__(256, 3) void edge_kernel(
    const float* __restrict__ ef, const int* __restrict__ ei,
    const float* __restrict__ b_val, const float* __restrict__ b_mul,
    float* __restrict__ out)
{
    extern __shared__ char smem[];
    u32 sb = smem_u32(smem);
    int tid = threadIdx.x, wid = tid >> 5, lane = tid & 31;
    int jhalf = blockIdx.y;
    int* idxb = (int*)(smem + E_IDX);   // [buf][128]: s at +0, r at +64

    // ---- B fill (once): permuted rows, xor-swizzled, single fp16 ----
    {
        int jl = tid >> 1, k0 = (tid & 1) * 32;
        int jgrp_ = jl >> 5, jj = jl & 31, ntb = jj >> 3, rr = jj & 7;
        int dd = (rr >> 1) * 4 + (ntb & 1) * 2 + (rr & 1);
        int jg = ((ntb < 2) ? 0 : 128) + jhalf * 64 + jgrp_ * 16 + dd;
        int xorm = (jl & 7) << 4;
        #pragma unroll
        for (int c = 0; c < 32; c += 2) {
            u32 off = (u32)(jl * 128) + (u32)(((k0 + c) * 2) ^ xorm);
            __half2 h2;
            h2.x = g_We[jg * 64 + k0 + c]; h2.y = g_We[jg * 64 + k0 + c + 1];
            *(__half2*)(smem + EB_ + off) = h2;
        }
    }

    int egrp = wid >> 2, jgrp = wid & 3;

    int jrow = jgrp * 32 + ((lane >> 4) & 1) * 8 + (lane & 7);
    u32 bRow = sb + EB_ + (u32)(jrow * 128);
    int bxor = (jrow & 7) << 4;
    int bk16 = ((lane >> 3) & 1) * 16;

    u32 aRow = sb + EA_ + (u32)((lane & 15) * 128);
    int axor = (lane & 7) << 4;
    int ak16 = (lane >> 4) * 16;

    int q = lane & 3;
    int dbase = jhalf * 64 + jgrp * 16 + q * 4;
    int dq8 = (dbase >> 2) * 8;             // paired P offset (halfs)
    const float4 bv4 = *(const float4*)&b_val[dbase];
    const float4 bm4 = *(const float4*)&b_mul[dbase];

    // A-fill lane mapping (constant)
    int fe = tid >> 2, fk0 = (tid & 3) * 16;
    int fxm = (fe & 7) << 4;

    const int stride = gridDim.x;
    const int ntiles = N_EDGES / 64;   // 12500
    int tile = blockIdx.x;

    // ---- prologue: fill A + idx for first tile ----
    if (tile < ntiles) {
        int e0 = tile * 64;
        if (tid < 64)       idxb[tid] = ei[e0 + tid];
        else if (tid < 128) idxb[tid] = ei[N_EDGES + e0 + tid - 64];
        const float4* src4 = (const float4*)&ef[(size_t)(e0 + fe) * ED + fk0];
        #pragma unroll
        for (int c = 0; c < 16; c += 4) {
            float4 xv = src4[c >> 2];
            __half2 h01 = __floats2half2_rn(xv.x, xv.y);
            __half2 h23 = __floats2half2_rn(xv.z, xv.w);
            u32 off = (u32)(fe * 128) + (u32)(((fk0 + c) * 2) ^ fxm);
            *(uint2*)(smem + EA_ + off) =
                make_uint2(*(u32*)&h01, *(u32*)&h23);
        }
    }
    __syncthreads();

    int buf = 0;
    for (; tile < ntiles; tile += stride) {
        float acc[2][4][4];
        #pragma unroll
        for (int mt = 0; mt < 2; mt++)
            #pragma unroll
            for (int nt = 0; nt < 4; nt++)
                #pragma unroll
                for (int j = 0; j < 4; j++) acc[mt][nt][j] = 0.f;

        #pragma unroll
        for (int kk = 0; kk < 4; kk++) {
            u32 akx = (u32)((kk * 32 + ak16) ^ axor);
            u32 p0, p1, p2, p3, q0, q1, q2, q3;
            ldsm4(aRow + (u32)((egrp * 32) * 128) + akx, p0, p1, p2, p3);
            ldsm4(aRow + (u32)((egrp * 32 + 16) * 128) + akx, q0, q1, q2, q3);
            u32 bkx = (u32)((kk * 32 + bk16) ^ bxor);
            #pragma unroll
            for (int np = 0; np < 2; np++) {
                u32 b0, b1, b2, b3;
                ldsm4(bRow + np * 2048 + bkx, b0, b1, b2, b3);
                mma16816h(acc[0][np * 2 + 0], p0, p1, p2, p3, b0, b1);
                mma16816h(acc[0][np * 2 + 1], p0, p1, p2, p3, b2, b3);
                mma16816h(acc[1][np * 2 + 0], q0, q1, q2, q3, b0, b1);
                mma16816h(acc[1][np * 2 + 1], q0, q1, q2, q3, b2, b3);
            }
        }
        __syncthreads();   // A smem consumed; safe to refill

        // ---- overlap: issue next tile's A fill + idx loads BEFORE epilogue ----
        int nxt = tile + stride;
        if (nxt < ntiles) {
            int e0n = nxt * 64;
            int* nb = idxb + (buf ^ 1) * 128;
            if (tid < 64)       nb[tid] = ei[e0n + tid];
            else if (tid < 128) nb[tid] = ei[N_EDGES + e0n + tid - 64];
            const float4* src4 = (const float4*)&ef[(size_t)(e0n + fe) * ED + fk0];
            #pragma unroll
            for (int c = 0; c < 16; c += 4) {
                float4 xv = src4[c >> 2];
                __half2 h01 = __floats2half2_rn(xv.x, xv.y);
                __half2 h23 = __floats2half2_rn(xv.z, xv.w);
                u32 off = (u32)(fe * 128) + (u32)(((fk0 + c) * 2) ^ fxm);
                *(uint2*)(smem + EA_ + off) =
                    make_uint2(*(u32*)&h01, *(u32*)&h23);
            }
        }

        // ---- register epilogue: paired 16B P gathers + red.v4 scatter ----
        const int* cb = idxb + buf * 128;
        #pragma unroll
        for (int mt = 0; mt < 2; mt++) {
            #pragma unroll
            for (int h = 0; h < 2; h++) {
                int e = egrp * 32 + mt * 16 + h * 8 + (lane >> 2);
                int s = cb[e];
                int r = cb[64 + e];
                uint4 us = *(const uint4*)&g_Ph[(size_t)s * 512 + dq8];
                uint4 ur = *(const uint4*)&g_Ph[(size_t)r * 512 + 256 + dq8];
                float2 sv01 = __half22float2(*(__half2*)&us.x);
                float2 sv23 = __half22float2(*(__half2*)&us.y);
                float2 sm01 = __half22float2(*(__half2*)&us.z);
                float2 sm23 = __half22float2(*(__half2*)&us.w);
                float2 rv01 = __half22float2(*(__half2*)&ur.x);
                float2 rv23 = __half22float2(*(__half2*)&ur.y);
                float2 rm01 = __half22float2(*(__half2*)&ur.z);
                float2 rm23 = __half22float2(*(__half2*)&ur.w);

                float v0 = acc[mt][0][2 * h + 0] + sv01.x + rv01.x + bv4.x;
                float v1 = acc[mt][0][2 * h + 1] + sv01.y + rv01.y + bv4.y;
                float v2 = acc[mt][1][2 * h + 0] + sv23.x + rv23.x + bv4.z;
                float v3 = acc[mt][1][2 * h + 1] + sv23.y + rv23.y + bv4.w;
                float m0 = acc[mt][2][2 * h + 0] + sm01.x + rm01.x + bm4.x;
                float m1 = acc[mt][2][2 * h + 1] + sm01.y + rm01.y + bm4.y;
                float m2 = acc[mt][3][2 * h + 0] + sm23.x + rm23.x + bm4.z;
                float m3 = acc[mt][3][2 * h + 1] + sm23.y + rm23.y + bm4.w;

                float g0 = softplus_f(v0) * sigmoid_f(m0);
                float g1 = softplus_f(v1) * sigmoid_f(m1);
                float g2 = softplus_f(v2) * sigmoid_f(m2);
                float g3 = softplus_f(v3) * sigmoid_f(m3);

                red4(out + (size_t)r * ND + dbase, g0, g1, g2, g3);
            }
        }
        __syncthreads();   // next tile's A fill complete before its MMA
        buf ^= 1;
    }
}

// ---------------------------------------------------------------------------
extern "C" void kernel_launch(void* const* d_in, const int* in_sizes, int n_in,
                              void* d_out, int out_size) {
    const float* x  = (const float*)d_in[0];
    const int*   ei = (const int*)  d_in[1];
    const float* ef = (const float*)d_in[2];
    const float* Wv = (const float*)d_in[3];
    const float* bv = (const float*)d_in[4];
    const float* Wm = (const float*)d_in[5];
    const float* bm = (const float*)d_in[6];
    float* out = (float*)d_out;

    cudaFuncSetAttribute(node_gemm_kernel,
                         cudaFuncAttributeMaxDynamicSharedMemorySize, NODE_SMEM);
    cudaFuncSetAttribute(edge_kernel,
                         cudaFuncAttributeMaxDynamicSharedMemorySize, EDGE_SMEM);

    int n4 = N_NODES * ND / 4;   // 1,600,000 float4
    prep_kernel<<<(n4 + 255) / 256, 256>>>(Wv, Wm, (float4*)out, n4);

    node_gemm_kernel<<<dim3(74, 2), 512, NODE_SMEM>>>(x);

    edge_kernel<<<dim3(222, 2), 256, EDGE_SMEM>>>(ef, ei, bv, bm, out);
}

// round 16
// speedup vs baseline: 1.2986x; 1.1321x over previous
#include <cuda_runtime.h>
#include <cuda_bf16.h>
#include <cuda_fp16.h>
#include <stdint.h>

#define N_NODES 50000
#define N_EDGES 800000
#define ND 128
#define ED 64
#define HID 320

typedef uint32_t u32;

// ---------------- device globals (allocation-guard safe) -------------------
// P layout (fp16, 512 cols/node):
//   [0:256)   sender part:   quad q (dims 4q..4q+3): cols q*8+0..3 = val, q*8+4..7 = mul
//   [256:512) receiver part: same structure
__device__ __half g_Ph[(size_t)N_NODES * 512];
__device__ __half g_Wn[512 * 128];               // node weights fp16, rows = P cols
__device__ __half g_We[256 * 64];                // edge weights fp16 [j][k]

// ---------------- helpers ----------------------------------------------------
__device__ __forceinline__ u32 smem_u32(const void* p) {
    u32 a;
    asm("{ .reg .u64 t; cvta.to.shared.u64 t, %1; cvt.u32.u64 %0, t; }" : "=r"(a) : "l"(p));
    return a;
}
__device__ __forceinline__ void ldsm4(u32 addr, u32& r0, u32& r1, u32& r2, u32& r3) {
    asm volatile("ldmatrix.sync.aligned.m8n8.x4.shared.b16 {%0,%1,%2,%3}, [%4];"
                 : "=r"(r0), "=r"(r1), "=r"(r2), "=r"(r3) : "r"(addr));
}
// fp32-acc fp16 MMA (node kernel)
__device__ __forceinline__ void mma16816h(float* d, u32 a0, u32 a1, u32 a2, u32 a3,
                                          u32 b0, u32 b1) {
    asm volatile(
        "mma.sync.aligned.m16n8k16.row.col.f32.f16.f16.f32 "
        "{%0,%1,%2,%3}, {%4,%5,%6,%7}, {%8,%9}, {%0,%1,%2,%3};"
        : "+f"(d[0]), "+f"(d[1]), "+f"(d[2]), "+f"(d[3])
        : "r"(a0), "r"(a1), "r"(a2), "r"(a3), "r"(b0), "r"(b1));
}
// fp16-acc fp16 MMA (edge kernel): D/C are 2 packed regs
__device__ __forceinline__ void mma16816hh(u32* d, u32 a0, u32 a1, u32 a2, u32 a3,
                                           u32 b0, u32 b1) {
    asm volatile(
        "mma.sync.aligned.m16n8k16.row.col.f16.f16.f16.f16 "
        "{%0,%1}, {%2,%3,%4,%5}, {%6,%7}, {%0,%1};"
        : "+r"(d[0]), "+r"(d[1])
        : "r"(a0), "r"(a1), "r"(a2), "r"(a3), "r"(b0), "r"(b1));
}
__device__ __forceinline__ void red4(float* p, float a, float b, float c, float d) {
    asm volatile("red.global.add.v4.f32 [%0], {%1,%2,%3,%4};"
                 :: "l"(p), "f"(a), "f"(b), "f"(c), "f"(d) : "memory");
}
__device__ __forceinline__ float softplus_f(float x) {
    return fmaxf(x, 0.f) + __logf(1.f + __expf(-fabsf(x)));
}
__device__ __forceinline__ float sigmoid_f(float x) {
    return __fdividef(1.f, 1.f + __expf(-x));
}

// ---------------------------------------------------------------------------
// prep: zero output + pack weights (fused, one launch)
// ---------------------------------------------------------------------------
__global__ void prep_kernel(const float* __restrict__ Wv,
                            const float* __restrict__ Wm,
                            float4* __restrict__ out, int n4) {
    int i = blockIdx.x * blockDim.x + threadIdx.x;
    if (i < n4) out[i] = make_float4(0.f, 0.f, 0.f, 0.f);
    if (i < 512 * 128) {
        int p = i >> 7, k = i & 127;
        int half = p >> 8;
        int q = (p & 255) >> 3, t = p & 7;
        int d = q * 4 + (t & 3);
        const float* W = (t < 4) ? Wv : Wm;
        g_Wn[i] = __float2half_rn(W[d * HID + half * 128 + k]);
    }
    if (i < 256 * 64) {
        int j = i >> 6, k = i & 63;
        float v = (j < 128) ? Wv[j * HID + 256 + k] : Wm[(j - 128) * HID + 256 + k];
        g_We[i] = __float2half_rn(v);
    }
}

// ---------------------------------------------------------------------------
// Node GEMM v14 (single fp16 term): P = Xh @ Wn^T.  (unchanged — ~65 us)
// Tile 128 nodes x 256 j, 512 thr / 16 warps, warp = 16n x 128j.
// ---------------------------------------------------------------------------
#define NSTR 136
#define N_B  0                      // 256*136*2 = 69632
#define N_A  69632                  // 128*136*2 = 34816 -> 104448
#define NODE_SMEM 104448

__global__ __launch_bounds__(512, 1) void node_gemm_kernel(const float* __restrict__ X) {
    extern __shared__ char smem[];
    u32 sb = smem_u32(smem);
    int tid = threadIdx.x, wid = tid >> 5, lane = tid & 31;
    int n0 = blockIdx.y * 256;

    {
        int j = tid >> 1, k0 = (tid & 1) * 64;
        #pragma unroll
        for (int c = 0; c < 64; c += 2) {
            __half2 h2;
            h2.x = g_Wn[(n0 + j) * 128 + k0 + c];
            h2.y = g_Wn[(n0 + j) * 128 + k0 + c + 1];
            *(__half2*)(smem + N_B + (j * NSTR + k0 + c) * 2) = h2;
        }
    }

    int egrp = wid >> 1, jgrp = wid & 1;
    u32 aA = sb + N_A + ((egrp * 16 + (lane & 15)) * NSTR + (lane >> 4) * 8) * 2;
    u32 bB = sb + N_B + ((jgrp * 128 + ((lane >> 4) & 1) * 8 + (lane & 7)) * NSTR) * 2
                 + ((lane >> 3) & 1) * 16;

    const int ntiles = (N_NODES + 127) / 128;   // 391
    for (int t = blockIdx.x; t < ntiles; t += gridDim.x) {
        int m0 = t * 128;
        {
            int row = tid >> 2, k0 = (tid & 3) * 32;
            int gm = m0 + row;
            #pragma unroll
            for (int c = 0; c < 32; c += 4) {
                float4 xv = make_float4(0.f, 0.f, 0.f, 0.f);
                if (gm < N_NODES) xv = *(const float4*)&X[(size_t)gm * ND + k0 + c];
                __half2 h01 = __floats2half2_rn(xv.x, xv.y);
                __half2 h23 = __floats2half2_rn(xv.z, xv.w);
                *(uint2*)(smem + N_A + (row * NSTR + k0 + c) * 2) =
                    make_uint2(*(u32*)&h01, *(u32*)&h23);
            }
        }
        __syncthreads();

        float acc[16][4];
        #pragma unroll
        for (int i = 0; i < 16; i++)
            #pragma unroll
            for (int j = 0; j < 4; j++) acc[i][j] = 0.f;

        #pragma unroll
        for (int kk = 0; kk < 8; kk++) {
            u32 a0, a1, a2, a3;
            ldsm4(aA + kk * 32, a0, a1, a2, a3);
            #pragma unroll
            for (int np = 0; np < 8; np++) {
                u32 b0, b1, b2, b3;
                ldsm4(bB + np * (16 * NSTR * 2) + kk * 32, b0, b1, b2, b3);
                mma16816h(acc[np * 2 + 0], a0, a1, a2, a3, b0, b1);
                mma16816h(acc[np * 2 + 1], a0, a1, a2, a3, b2, b3);
            }
        }

        int nodeLo = m0 + egrp * 16 + (lane >> 2);
        int jbase = n0 + jgrp * 128 + (lane & 3) * 2;
        #pragma unroll
        for (int nt = 0; nt < 16; nt++) {
            if (nodeLo < N_NODES)
                *(__half2*)&g_Ph[(size_t)nodeLo * 512 + jbase + nt * 8] =
                    __floats2half2_rn(acc[nt][0], acc[nt][1]);
            if (nodeLo + 8 < N_NODES)
                *(__half2*)&g_Ph[(size_t)(nodeLo + 8) * 512 + jbase + nt * 8] =
                    __floats2half2_rn(acc[nt][2], acc[nt][3]);
        }
        __syncthreads();
    }
}

// ---------------------------------------------------------------------------
// Edge kernel v15: v11 shape + fp16 accumulators -> 64 regs, 4 CTAs/SM.
// single-term fp16 MMA, paired 16B P gathers, fill-epilogue overlap.
// 256 thr / 8 warps. Tile 64 edges x 128 j (jhalf class).
// ---------------------------------------------------------------------------
#define EB_  0                      // 128 rows * 128B = 16384
#define EA_  16384                  // 64 rows * 128B = 8192 -> 24576
#define E_IDX 24576                 // 2 bufs * 128 ints -> 25600
#define EDGE_SMEM 25600

__global__ __launch_bounds__(256, 4) void edge_kernel(
    const float* __restrict__ ef, const int* __restrict__ ei,
    const float* __restrict__ b_val, const float* __restrict__ b_mul,
    float* __restrict__ out)
{
    extern __shared__ char smem[];
    u32 sb = smem_u32(smem);
    int tid = threadIdx.x, wid = tid >> 5, lane = tid & 31;
    int jhalf = blockIdx.y;
    int* idxb = (int*)(smem + E_IDX);   // [buf][128]: s at +0, r at +64

    // ---- B fill (once): permuted rows, xor-swizzled, single fp16 ----
    {
        int jl = tid >> 1, k0 = (tid & 1) * 32;
        int jgrp_ = jl >> 5, jj = jl & 31, ntb = jj >> 3, rr = jj & 7;
        int dd = (rr >> 1) * 4 + (ntb & 1) * 2 + (rr & 1);
        int jg = ((ntb < 2) ? 0 : 128) + jhalf * 64 + jgrp_ * 16 + dd;
        int xorm = (jl & 7) << 4;
        #pragma unroll
        for (int c = 0; c < 32; c += 2) {
            u32 off = (u32)(jl * 128) + (u32)(((k0 + c) * 2) ^ xorm);
            __half2 h2;
            h2.x = g_We[jg * 64 + k0 + c]; h2.y = g_We[jg * 64 + k0 + c + 1];
            *(__half2*)(smem + EB_ + off) = h2;
        }
    }

    int egrp = wid >> 2, jgrp = wid & 3;

    int jrow = jgrp * 32 + ((lane >> 4) & 1) * 8 + (lane & 7);
    u32 bRow = sb + EB_ + (u32)(jrow * 128);
    int bxor = (jrow & 7) << 4;
    int bk16 = ((lane >> 3) & 1) * 16;

    u32 aRow = sb + EA_ + (u32)((lane & 15) * 128);
    int axor = (lane & 7) << 4;
    int ak16 = (lane >> 4) * 16;

    int q = lane & 3;
    int dbase = jhalf * 64 + jgrp * 16 + q * 4;
    int dq8 = (dbase >> 2) * 8;             // paired P offset (halfs)
    const float4 bv4 = *(const float4*)&b_val[dbase];
    const float4 bm4 = *(const float4*)&b_mul[dbase];

    // A-fill lane mapping (constant)
    int fe = tid >> 2, fk0 = (tid & 3) * 16;
    int fxm = (fe & 7) << 4;

    const int stride = gridDim.x;
    const int ntiles = N_EDGES / 64;   // 12500
    int tile = blockIdx.x;

    // ---- prologue: fill A + idx for first tile ----
    if (tile < ntiles) {
        int e0 = tile * 64;
        if (tid < 64)       idxb[tid] = ei[e0 + tid];
        else if (tid < 128) idxb[tid] = ei[N_EDGES + e0 + tid - 64];
        const float4* src4 = (const float4*)&ef[(size_t)(e0 + fe) * ED + fk0];
        #pragma unroll
        for (int c = 0; c < 16; c += 4) {
            float4 xv = src4[c >> 2];
            __half2 h01 = __floats2half2_rn(xv.x, xv.y);
            __half2 h23 = __floats2half2_rn(xv.z, xv.w);
            u32 off = (u32)(fe * 128) + (u32)(((fk0 + c) * 2) ^ fxm);
            *(uint2*)(smem + EA_ + off) =
                make_uint2(*(u32*)&h01, *(u32*)&h23);
        }
    }
    __syncthreads();

    int buf = 0;
    for (; tile < ntiles; tile += stride) {
        // ---- MMA: fp16 accumulators (acc[mt][nt][h] packs dim-bits 0/1) ----
        u32 acc[2][4][2];
        #pragma unroll
        for (int mt = 0; mt < 2; mt++)
            #pragma unroll
            for (int nt = 0; nt < 4; nt++) {
                acc[mt][nt][0] = 0u; acc[mt][nt][1] = 0u;
            }

        #pragma unroll
        for (int kk = 0; kk < 4; kk++) {
            u32 akx = (u32)((kk * 32 + ak16) ^ axor);
            u32 p0, p1, p2, p3, q0, q1, q2, q3;
            ldsm4(aRow + (u32)((egrp * 32) * 128) + akx, p0, p1, p2, p3);
            ldsm4(aRow + (u32)((egrp * 32 + 16) * 128) + akx, q0, q1, q2, q3);
            u32 bkx = (u32)((kk * 32 + bk16) ^ bxor);
            #pragma unroll
            for (int np = 0; np < 2; np++) {
                u32 b0, b1, b2, b3;
                ldsm4(bRow + np * 2048 + bkx, b0, b1, b2, b3);
                mma16816hh(acc[0][np * 2 + 0], p0, p1, p2, p3, b0, b1);
                mma16816hh(acc[0][np * 2 + 1], p0, p1, p2, p3, b2, b3);
                mma16816hh(acc[1][np * 2 + 0], q0, q1, q2, q3, b0, b1);
                mma16816hh(acc[1][np * 2 + 1], q0, q1, q2, q3, b2, b3);
            }
        }
        __syncthreads();   // A smem consumed; safe to refill

        // ---- overlap: issue next tile's A fill + idx loads BEFORE epilogue ----
        int nxt = tile + stride;
        if (nxt < ntiles) {
            int e0n = nxt * 64;
            int* nb = idxb + (buf ^ 1) * 128;
            if (tid < 64)       nb[tid] = ei[e0n + tid];
            else if (tid < 128) nb[tid] = ei[N_EDGES + e0n + tid - 64];
            const float4* src4 = (const float4*)&ef[(size_t)(e0n + fe) * ED + fk0];
            #pragma unroll
            for (int c = 0; c < 16; c += 4) {
                float4 xv = src4[c >> 2];
                __half2 h01 = __floats2half2_rn(xv.x, xv.y);
                __half2 h23 = __floats2half2_rn(xv.z, xv.w);
                u32 off = (u32)(fe * 128) + (u32)(((fk0 + c) * 2) ^ fxm);
                *(uint2*)(smem + EA_ + off) =
                    make_uint2(*(u32*)&h01, *(u32*)&h23);
            }
        }

        // ---- register epilogue: paired 16B P gathers + red.v4 scatter ----
        const int* cb = idxb + buf * 128;
        #pragma unroll
        for (int mt = 0; mt < 2; mt++) {
            #pragma unroll
            for (int h = 0; h < 2; h++) {
                int e = egrp * 32 + mt * 16 + h * 8 + (lane >> 2);
                int s = cb[e];
                int r = cb[64 + e];
                uint4 us = *(const uint4*)&g_Ph[(size_t)s * 512 + dq8];
                uint4 ur = *(const uint4*)&g_Ph[(size_t)r * 512 + 256 + dq8];
                float2 sv01 = __half22float2(*(__half2*)&us.x);
                float2 sv23 = __half22float2(*(__half2*)&us.y);
                float2 sm01 = __half22float2(*(__half2*)&us.z);
                float2 sm23 = __half22float2(*(__half2*)&us.w);
                float2 rv01 = __half22float2(*(__half2*)&ur.x);
                float2 rv23 = __half22float2(*(__half2*)&ur.y);
                float2 rm01 = __half22float2(*(__half2*)&ur.z);
                float2 rm23 = __half22float2(*(__half2*)&ur.w);

                float2 qv01 = __half22float2(*(__half2*)&acc[mt][0][h]);
                float2 qv23 = __half22float2(*(__half2*)&acc[mt][1][h]);
                float2 qm01 = __half22float2(*(__half2*)&acc[mt][2][h]);
                float2 qm23 = __half22float2(*(__half2*)&acc[mt][3][h]);

                float v0 = qv01.x + sv01.x + rv01.x + bv4.x;
                float v1 = qv01.y + sv01.y + rv01.y + bv4.y;
                float v2 = qv23.x + sv23.x + rv23.x + bv4.z;
                float v3 = qv23.y + sv23.y + rv23.y + bv4.w;
                float m0 = qm01.x + sm01.x + rm01.x + bm4.x;
                float m1 = qm01.y + sm01.y + rm01.y + bm4.y;
                float m2 = qm23.x + sm23.x + rm23.x + bm4.z;
                float m3 = qm23.y + sm23.y + rm23.y + bm4.w;

                float g0 = softplus_f(v0) * sigmoid_f(m0);
                float g1 = softplus_f(v1) * sigmoid_f(m1);
                float g2 = softplus_f(v2) * sigmoid_f(m2);
                float g3 = softplus_f(v3) * sigmoid_f(m3);

                red4(out + (size_t)r * ND + dbase, g0, g1, g2, g3);
            }
        }
        __syncthreads();   // next tile's A fill complete before its MMA
        buf ^= 1;
    }
}

// ---------------------------------------------------------------------------
extern "C" void kernel_launch(void* const* d_in, const int* in_sizes, int n_in,
                              void* d_out, int out_size) {
    const float* x  = (const float*)d_in[0];
    const int*   ei = (const int*)  d_in[1];
    const float* ef = (const float*)d_in[2];
    const float* Wv = (const float*)d_in[3];
    const float* bv = (const float*)d_in[4];
    const float* Wm = (const float*)d_in[5];
    const float* bm = (const float*)d_in[6];
    float* out = (float*)d_out;

    cudaFuncSetAttribute(node_gemm_kernel,
                         cudaFuncAttributeMaxDynamicSharedMemorySize, NODE_SMEM);
    cudaFuncSetAttribute(edge_kernel,
                         cudaFuncAttributeMaxDynamicSharedMemorySize, EDGE_SMEM);

    int n4 = N_NODES * ND / 4;   // 1,600,000 float4
    prep_kernel<<<(n4 + 255) / 256, 256>>>(Wv, Wm, (float4*)out, n4);

    node_gemm_kernel<<<dim3(74, 2), 512, NODE_SMEM>>>(x);

    edge_kernel<<<dim3(296, 2), 256, EDGE_SMEM>>>(ef, ei, bv, bm, out);
}